// round 9
// baseline (speedup 1.0000x reference)
#include <cuda_runtime.h>
#include <cuda_fp16.h>
#include <cstdint>

// Problem constants
#define NN 2048
#define RR 4
#define BB 4096
#define NSEG 32
#define SEGLEN (NN / NSEG)

// GEMM tiling: CTA 256(M=batch) x 128(N=outputs), 16 warps @ 64x32 (4M x 4N)
#define BM 256
#define BN 128
#define BKK 64
#define NCH (NN / BKK)           // 32 chunks
#define SSTRIDE 72               // smem row stride fp16 (64 data + 8 pad) = 144B
#define ROWB (SSTRIDE * 2)       // 144 B, conflict-free ldmatrix
#define ATILEB (BM * ROWB)       // 36864 B
#define BTILEB (BN * ROWB)       // 18432 B
#define STAGEB (ATILEB + BTILEB) // 55296 B
#define NSTAGE 3
#define DSMEM (NSTAGE * STAGEB)  // 165888 B

// convert/scan fusion split
#define CONV_BLOCKS ((BB * NN / 4) / 256)   // 8192
#define SCAN_BLOCKS (NN / 256)              // 8 per segment

// Scratch
__device__ __align__(256) float g_S[NSEG * NN];
__device__ __align__(256) float g_P[NN * NN];        // P[c][d] = T[d,c]
__device__ __align__(256) __half g_Mf[NN * NN];      // M[a][c], row-major
__device__ __align__(256) __half g_xf[(size_t)BB * NN];

// ---------------------------------------------------------------------------
__device__ __forceinline__ uint32_t cvta_smem(const void* p) {
    uint32_t a;
    asm("{ .reg .u64 t; cvta.to.shared.u64 t, %1; cvt.u32.u64 %0, t; }" : "=r"(a) : "l"(p));
    return a;
}
__device__ __forceinline__ void cpasync16(uint32_t s, const void* g) {
    asm volatile("cp.async.cg.shared.global [%0], [%1], 16;" :: "r"(s), "l"(g));
}
__device__ __forceinline__ void cp_commit() {
    asm volatile("cp.async.commit_group;" ::: "memory");
}
template <int N> __device__ __forceinline__ void cp_wait() {
    asm volatile("cp.async.wait_group %0;" :: "n"(N) : "memory");
}
__device__ __forceinline__ void ldm_x4(uint32_t* r, uint32_t addr) {
    asm volatile("ldmatrix.sync.aligned.m8n8.x4.shared.b16 {%0,%1,%2,%3}, [%4];"
                 : "=r"(r[0]), "=r"(r[1]), "=r"(r[2]), "=r"(r[3]) : "r"(addr));
}
__device__ __forceinline__ void mma16816(float* c, const uint32_t* a, const uint32_t* b) {
    asm volatile(
        "mma.sync.aligned.m16n8k16.row.col.f32.f16.f16.f32 "
        "{%0,%1,%2,%3}, {%4,%5,%6,%7}, {%8,%9}, {%0,%1,%2,%3};"
        : "+f"(c[0]), "+f"(c[1]), "+f"(c[2]), "+f"(c[3])
        : "r"(a[0]), "r"(a[1]), "r"(a[2]), "r"(a[3]), "r"(b[0]), "r"(b[1]));
}

// ---------------------------------------------------------------------------
// Kernel 1 (fused): convert x to fp16 + scan pass 1
// ---------------------------------------------------------------------------
__global__ void fused_conv_scan1(const float* __restrict__ x,
                                 const float* __restrict__ G,
                                 const float* __restrict__ H) {
    if (blockIdx.x < CONV_BLOCKS) {
        const size_t i = ((size_t)blockIdx.x * blockDim.x + threadIdx.x) * 4;
        const float4 v = *reinterpret_cast<const float4*>(x + i);
        __half2* dh = reinterpret_cast<__half2*>(&g_xf[i]);
        dh[0] = __half2(__float2half(v.x), __float2half(v.y));
        dh[1] = __half2(__float2half(v.z), __float2half(v.w));
    } else {
        const int bid = blockIdx.x - CONV_BLOCKS;
        const int seg = bid / SCAN_BLOCKS;
        const int d = (bid % SCAN_BLOCKS) * blockDim.x + threadIdx.x;
        const int cbeg = seg * SEGLEN;
        float acc = 0.0f;
#pragma unroll 4
        for (int c = cbeg; c < cbeg + SEGLEN; ++c) {
            const int s = (d + c) & (NN - 1);
            float v = G[s] * H[c];
            v = fmaf(G[NN + s], H[NN + c], v);
            v = fmaf(G[2 * NN + s], H[2 * NN + c], v);
            v = fmaf(G[3 * NN + s], H[3 * NN + c], v);
            acc += v;
        }
        g_S[seg * NN + d] = acc;
    }
}

// ---------------------------------------------------------------------------
// Kernel 2: per-segment prefix with segment offset.  P[c][d] = T[d,c]
// ---------------------------------------------------------------------------
__global__ void scan_pass2(const float* __restrict__ G, const float* __restrict__ H) {
    const int d = blockIdx.x * blockDim.x + threadIdx.x;
    const int seg = blockIdx.y;
    float acc = 0.0f;
#pragma unroll
    for (int s2 = 0; s2 < NSEG; ++s2)
        if (s2 < seg) acc += g_S[s2 * NN + d];
    const int cbeg = seg * SEGLEN;
#pragma unroll 4
    for (int c = cbeg; c < cbeg + SEGLEN; ++c) {
        const int s = (d + c) & (NN - 1);
        float v = G[s] * H[c];
        v = fmaf(G[NN + s], H[NN + c], v);
        v = fmaf(G[2 * NN + s], H[2 * NN + c], v);
        v = fmaf(G[3 * NN + s], H[3 * NN + c], v);
        acc += v;
        g_P[c * NN + d] = acc;
    }
}

// ---------------------------------------------------------------------------
// Kernel 3: M[a][c] = 2*P[c][d] - P[NN-1][d], d=(a-c)%n; transpose + fp16
// ---------------------------------------------------------------------------
__global__ void build_m_kernel() {
    __shared__ float tile[32][33];
    const int a0 = blockIdx.x * 32;
    const int c0 = blockIdx.y * 32;
    const int tx = threadIdx.x;
#pragma unroll
    for (int yy = threadIdx.y; yy < 32; yy += 8) {
        const int c = c0 + yy;
        const int d = (a0 + tx - c) & (NN - 1);
        tile[yy][tx] = 2.0f * g_P[c * NN + d] - g_P[(NN - 1) * NN + d];
    }
    __syncthreads();
#pragma unroll
    for (int yy = threadIdx.y; yy < 32; yy += 8) {
        const int a = a0 + yy;
        const int c = c0 + tx;
        g_Mf[(size_t)a * NN + c] = __float2half(tile[tx][yy]);
    }
}

// ---------------------------------------------------------------------------
// Kernel 4: fp16 HMMA GEMM.  C[b][a] = sum_c x[b][c] * M[a][c]
// CTA 256x128, 512 threads, 16 warps @ 64x32 (4M x 4N), 3-stage cp.async.
// Register-double-buffered fragments: ldmatrix(ks+1) issued before MMA(ks).
// ---------------------------------------------------------------------------
__global__ __launch_bounds__(512, 1)
void gemm_mma(float* __restrict__ C) {
    extern __shared__ char dsm[];
    const uint32_t sb = cvta_smem(dsm);

    const int tid = threadIdx.x;
    const int wid = tid >> 5;
    const int lid = tid & 31;
    const int m0 = blockIdx.y * BM;
    const int n0 = blockIdx.x * BN;

    const int warp_m = (wid & 3) * 64;   // 4 warps in M -> 256
    const int warp_n = (wid >> 2) * 32;  // 4 warps in N -> 128

    const char* gA = (const char*)g_xf + (size_t)m0 * (NN * 2);
    const char* gB = (const char*)g_Mf + (size_t)n0 * (NN * 2);

    const int lda_row = tid >> 1;
    const int lda_half = (tid & 1) * 64;
    const int ldb_row = tid >> 2;
    const int ldb_q = (tid & 3) * 32;

    auto load_chunk = [&](int ch) {
        const uint32_t st = sb + (uint32_t)(ch % NSTAGE) * STAGEB;
        {
            const char* g = gA + (size_t)lda_row * (NN * 2) + ch * (BKK * 2) + lda_half;
            const uint32_t s = st + lda_row * ROWB + lda_half;
#pragma unroll
            for (int i = 0; i < 4; ++i) cpasync16(s + i * 16, g + i * 16);
        }
        {
            const char* g = gB + (size_t)ldb_row * (NN * 2) + ch * (BKK * 2) + ldb_q;
            const uint32_t s = st + ATILEB + ldb_row * ROWB + ldb_q;
#pragma unroll
            for (int i = 0; i < 2; ++i) cpasync16(s + i * 16, g + i * 16);
        }
        cp_commit();
    };

    float acc[4][4][4];
#pragma unroll
    for (int i = 0; i < 4; ++i)
#pragma unroll
        for (int j = 0; j < 4; ++j)
#pragma unroll
            for (int q = 0; q < 4; ++q) acc[i][j][q] = 0.0f;

    const uint32_t a_off0 = (uint32_t)(warp_m + (lid & 15)) * ROWB + ((lid >> 4) * 8) * 2;
    const uint32_t b_off0 =
        (uint32_t)(warp_n + ((lid >> 4) << 3) + (lid & 7)) * ROWB + (((lid >> 3) & 1) * 8) * 2;

    uint32_t af[2][4][4], bf[2][2][4];

    auto load_frags = [&](int buf, uint32_t tA, uint32_t tB, int kk) {
#pragma unroll
        for (int i = 0; i < 4; ++i)
            ldm_x4(af[buf][i], tA + a_off0 + (uint32_t)(i * 16) * ROWB + kk * 2);
#pragma unroll
        for (int j = 0; j < 2; ++j)
            ldm_x4(bf[buf][j], tB + b_off0 + (uint32_t)(j * 16) * ROWB + kk * 2);
    };

    auto do_mmas = [&](int buf) {
#pragma unroll
        for (int i = 0; i < 4; ++i)
#pragma unroll
            for (int j = 0; j < 4; ++j)
                mma16816(acc[i][j], af[buf][i], &bf[buf][j >> 1][(j & 1) * 2]);
    };

    load_chunk(0);
    load_chunk(1);

    for (int ch = 0; ch < NCH; ++ch) {
        cp_wait<1>();
        __syncthreads();
        if (ch + 2 < NCH) load_chunk(ch + 2);

        const uint32_t st = sb + (uint32_t)(ch % NSTAGE) * STAGEB;
        const uint32_t tA = st;
        const uint32_t tB = st + ATILEB;

        load_frags(0, tA, tB, 0);
#pragma unroll
        for (int ks = 0; ks < 4; ++ks) {
            if (ks < 3) load_frags((ks + 1) & 1, tA, tB, (ks + 1) * 16);
            do_mmas(ks & 1);
        }
    }

    // epilogue
    const int er = lid >> 2;
    const int ec = (lid & 3) * 2;
#pragma unroll
    for (int i = 0; i < 4; ++i) {
        const int row = m0 + warp_m + i * 16 + er;
#pragma unroll
        for (int j = 0; j < 4; ++j) {
            const int col = n0 + warp_n + j * 8 + ec;
            float2* p0 = reinterpret_cast<float2*>(C + (size_t)row * NN + col);
            float2* p1 = reinterpret_cast<float2*>(C + (size_t)(row + 8) * NN + col);
            *p0 = make_float2(acc[i][j][0], acc[i][j][1]);
            *p1 = make_float2(acc[i][j][2], acc[i][j][3]);
        }
    }
}

// ---------------------------------------------------------------------------
extern "C" void kernel_launch(void* const* d_in, const int* in_sizes, int n_in,
                              void* d_out, int out_size) {
    const float* x = (const float*)d_in[0];  // (BB, NN)
    const float* G = (const float*)d_in[1];  // (RR, NN)
    const float* H = (const float*)d_in[2];  // (RR, NN)
    float* out = (float*)d_out;              // (BB, NN)

    cudaFuncSetAttribute(gemm_mma, cudaFuncAttributeMaxDynamicSharedMemorySize, DSMEM);

    fused_conv_scan1<<<CONV_BLOCKS + NSEG * SCAN_BLOCKS, 256>>>(x, G, H);
    scan_pass2<<<dim3(NN / 256, NSEG), 256>>>(G, H);
    build_m_kernel<<<dim3(NN / 32, NN / 32), dim3(32, 8)>>>();
    gemm_mma<<<dim3(NN / BN, BB / BM), 512, DSMEM>>>(out);
}